// round 11
// baseline (speedup 1.0000x reference)
#include <cuda_runtime.h>
#include <cuda_fp16.h>
#include <cstdint>

#define NN   10000
#define EE   160000
#define CIN  1024
#define HID  1024
#define COUT 512
#define KH   1024
#define MPAD 10112           // padded row allocation (>= 105*96 = 10080)
#define MT   96              // CTA M tile
#define NT2  256             // CTA N tile
#define MTILES 105           // ceil(10000/96)
#define PB   200             // stats partial blocks
#define GN_EPS 1e-5f
#define SLOPE  0.1f

// ---------------- scratch (static device globals; no runtime alloc) ----------------
__device__ __half g_h1[(size_t)NN * HID];           // h = GEMM1 out (fp16)
__device__ __half g_h2[(size_t)NN * HID];           // agg1 out (fp16)
__device__ __half g_a1h[(size_t)MPAD * KH];         // GEMM1 A (fp16)
__device__ __half g_a2h[(size_t)MPAD * KH];         // GEMM2 A = agg2 out (fp16)
__device__ __half g_b1h[(size_t)KH * HID];          // GEMM1 B [k][n] = fp16(W1)
__device__ __half g_b2h[(size_t)KH * HID];          // GEMM2 B [k][n] = fp16([Wm|Ws])
__device__ float g_alpha[CIN];
__device__ float g_beta[CIN];
__device__ float g_ps[(size_t)PB * CIN];            // stats partial sums
__device__ float g_pq[(size_t)PB * CIN];            // stats partial sumsq
__device__ float g_dinv[NN];
__device__ int   g_cnt[NN];
__device__ int   g_rowptr[NN + 1];
__device__ int   g_cur[NN];
__device__ int   g_srcs[EE];
__device__ int   g_dsts[EE];
__device__ int   g_cols[EE];
__device__ float g_wt[EE];

// ---------------- PTX helpers ----------------
__device__ __forceinline__ unsigned smem_u32(const void* p) {
    return (unsigned)__cvta_generic_to_shared(p);
}
__device__ __forceinline__ void cpa16s(unsigned dst, const void* src) {
    asm volatile("cp.async.cg.shared.global [%0], [%1], 16;" :: "r"(dst), "l"(src) : "memory");
}
__device__ __forceinline__ void ldsm4(unsigned* r, const void* p) {
    unsigned a = smem_u32(p);
    asm volatile("ldmatrix.sync.aligned.m8n8.x4.shared.b16 {%0,%1,%2,%3}, [%4];"
                 : "=r"(r[0]), "=r"(r[1]), "=r"(r[2]), "=r"(r[3]) : "r"(a));
}
__device__ __forceinline__ void ldsm4t(unsigned* r, const void* p) {
    unsigned a = smem_u32(p);
    asm volatile("ldmatrix.sync.aligned.m8n8.x4.trans.shared.b16 {%0,%1,%2,%3}, [%4];"
                 : "=r"(r[0]), "=r"(r[1]), "=r"(r[2]), "=r"(r[3]) : "r"(a));
}
__device__ __forceinline__ void mma16816h(float* d, const unsigned* a, const unsigned* b) {
    asm volatile("mma.sync.aligned.m16n8k16.row.col.f32.f16.f16.f32 "
                 "{%0,%1,%2,%3}, {%4,%5,%6,%7}, {%8,%9}, {%0,%1,%2,%3};"
                 : "+f"(d[0]), "+f"(d[1]), "+f"(d[2]), "+f"(d[3])
                 : "r"(a[0]), "r"(a[1]), "r"(a[2]), "r"(a[3]), "r"(b[0]), "r"(b[1]));
}

// ---------------- edge-chain kernels (side stream) ----------------
__global__ void k_zero_cnt() {
    int i = blockIdx.x * blockDim.x + threadIdx.x;
    if (i < NN) g_cnt[i] = 0;
}

// convert + degree count; int64/int32 detection done per-block (L1-hot)
__global__ void k_convert(const void* __restrict__ edges) {
    __shared__ int sh_is64;
    if (threadIdx.x == 0) {
        const int* e = (const int*)edges;
        int is64 = 1;
        for (int j = 0; j < 64; ++j)
            if (e[2 * j + 1] != 0) { is64 = 0; break; }
        sh_is64 = is64;
    }
    __syncthreads();
    int i = blockIdx.x * blockDim.x + threadIdx.x;
    if (i >= EE) return;
    int s, d;
    if (sh_is64) {
        const long long* e = (const long long*)edges;
        s = (int)e[i];  d = (int)e[EE + i];
    } else {
        const int* e = (const int*)edges;
        s = e[i];  d = e[EE + i];
    }
    g_srcs[i] = s;  g_dsts[i] = d;
    atomicAdd(&g_cnt[d], 1);
}

// blocked single-pass exclusive scan (1024 thr x 10 elems) -> rowptr/cur/dinv
__global__ void k_scan() {
    __shared__ int sh[1024];
    const int t = threadIdx.x;
    const int base = t * 10;
    int v[10], loc[10], run = 0;
    #pragma unroll
    for (int j = 0; j < 10; ++j) {
        int idx = base + j;
        v[j] = (idx < NN) ? g_cnt[idx] : 0;
        loc[j] = run;
        run += v[j];
    }
    sh[t] = run;
    __syncthreads();
    for (int off = 1; off < 1024; off <<= 1) {
        int add = (t >= off) ? sh[t - off] : 0;
        __syncthreads();
        sh[t] += add;
        __syncthreads();
    }
    int pre = (t > 0) ? sh[t - 1] : 0;
    #pragma unroll
    for (int j = 0; j < 10; ++j) {
        int idx = base + j;
        if (idx < NN) {
            int ex = pre + loc[j];
            g_rowptr[idx] = ex;
            g_cur[idx]    = ex;
            g_dinv[idx]   = rsqrtf((float)(v[j] + 1));   // +1 self loop
        }
    }
    if (t == 1023) g_rowptr[NN] = sh[1023];
}

__global__ void k_fill() {
    int i = blockIdx.x * blockDim.x + threadIdx.x;
    if (i >= EE) return;
    int d = g_dsts[i];
    int s = g_srcs[i];
    int pos = atomicAdd(&g_cur[d], 1);
    g_cols[pos] = s;
    g_wt[pos]   = g_dinv[s] * g_dinv[d];
}

// ---------------- dense-chain kernels ----------------
// stats: atomic-free partials (no zero dependency — launches at t=0)
__global__ void k_stats(const float* __restrict__ x) {
    const int t = threadIdx.x;
    const int b = blockIdx.x;
    float s0 = 0.f, s1 = 0.f, s2 = 0.f, s3 = 0.f;
    float q0 = 0.f, q1 = 0.f, q2 = 0.f, q3 = 0.f;
    for (int r = b; r < NN; r += PB) {
        const float* row = x + (size_t)r * CIN;
        float v0 = row[t];       s0 += v0; q0 += v0 * v0;
        float v1 = row[t + 256]; s1 += v1; q1 += v1 * v1;
        float v2 = row[t + 512]; s2 += v2; q2 += v2 * v2;
        float v3 = row[t + 768]; s3 += v3; q3 += v3 * v3;
    }
    float* ps = g_ps + (size_t)b * CIN;
    float* pq = g_pq + (size_t)b * CIN;
    ps[t]       = s0; pq[t]       = q0;
    ps[t + 256] = s1; pq[t + 256] = q1;
    ps[t + 512] = s2; pq[t + 512] = q2;
    ps[t + 768] = s3; pq[t + 768] = q3;
}

// reduce partials + compute alpha/beta
__global__ void k_fin(const float* __restrict__ gw,
                      const float* __restrict__ gb,
                      const float* __restrict__ gms) {
    int i = blockIdx.x * blockDim.x + threadIdx.x;   // 8 x 128 = 1024
    if (i >= CIN) return;
    float sum = 0.f, sq = 0.f;
    #pragma unroll 8
    for (int j = 0; j < PB; ++j) {
        sum += g_ps[(size_t)j * CIN + i];
        sq  += g_pq[(size_t)j * CIN + i];
    }
    float mean = sum * (1.0f / NN);
    float ex2  = sq  * (1.0f / NN);
    float s    = gms[i];
    float var  = ex2 - 2.f * s * mean * mean + s * s * mean * mean;
    float rstd = rsqrtf(var + GN_EPS);
    float al   = rstd * gw[i];
    g_alpha[i] = al;
    g_beta[i]  = gb[i] - s * mean * al;
}

// A1 = fp16(affine(x)), 4-wide vectorized
__global__ void k_build_a1(const float* __restrict__ x) {
    int i = blockIdx.x * blockDim.x + threadIdx.x;    // over NN*CIN/4
    if (i >= NN * CIN / 4) return;
    int k4 = (i & 255) << 2;
    float4 xv = ((const float4*)x)[i];
    float a0 = g_alpha[k4],     a1 = g_alpha[k4 + 1];
    float a2 = g_alpha[k4 + 2], a3 = g_alpha[k4 + 3];
    float b0 = g_beta[k4],      b1 = g_beta[k4 + 1];
    float b2 = g_beta[k4 + 2],  b3 = g_beta[k4 + 3];
    __half2 h0 = __floats2half2_rn(fmaf(xv.x, a0, b0), fmaf(xv.y, a1, b1));
    __half2 h1 = __floats2half2_rn(fmaf(xv.z, a2, b2), fmaf(xv.w, a3, b3));
    __half2* o = (__half2*)g_a1h + (size_t)i * 2;
    o[0] = h0;  o[1] = h1;
}

// B planes, 4-wide vectorized: g_b1h = fp16(W1); g_b2h = fp16([Wm|Ws])
__global__ void k_build_w(const float* __restrict__ W1,
                          const float* __restrict__ Wm,
                          const float* __restrict__ Ws) {
    int i = blockIdx.x * blockDim.x + threadIdx.x;    // over CIN*HID/4
    if (i >= CIN * HID / 4) return;
    int k  = i >> 8;
    int n4 = (i & 255) << 2;
    float4 w1 = ((const float4*)W1)[i];
    __half2* o1 = (__half2*)g_b1h + (size_t)i * 2;
    o1[0] = __floats2half2_rn(w1.x, w1.y);
    o1[1] = __floats2half2_rn(w1.z, w1.w);
    float4 w2 = (n4 < COUT)
        ? *(const float4*)(Wm + (size_t)k * COUT + n4)
        : *(const float4*)(Ws + (size_t)k * COUT + n4 - COUT);
    __half2* o2 = (__half2*)g_b2h + (size_t)i * 2;
    o2[0] = __floats2half2_rn(w2.x, w2.y);
    o2[1] = __floats2half2_rn(w2.z, w2.w);
}

// ---------------- fp16 tensor-core GEMM ----------------
// CTA 96x256, 256 threads (8 warps of 48x64), BK=64, 3-stage cp.async ring.
// noff: N-column offset (GEMM1 strips launch grid (1,105) with noff=strip*256).
// MODE 0: g_h1 (fp16) = A1 @ B1        MODE 1: out (f32) = A2 @ B2 + bias
template <int MODE>
__global__ void __launch_bounds__(256, 1)
k_mma(const float* __restrict__ bias0, const float* __restrict__ bias1,
      float* __restrict__ Cout, int noff)
{
    extern __shared__ __half smh[];
    const __half* __restrict__ A = (MODE == 0) ? g_a1h : g_a2h;
    const __half* __restrict__ B = (MODE == 0) ? g_b1h : g_b2h;

    constexpr int STA = MT * 72;             // A tile 96x64, pad 64->72
    constexpr int STB = 64 * 264;            // B tile 64x256, pad 256->264
    constexpr int STG = STA + STB;           // 23808 halfs / stage

    const int tid  = threadIdx.x;
    const int warp = tid >> 5;
    const int lane = tid & 31;
    const int bm0  = blockIdx.y * MT;
    const int bn0  = blockIdx.x * NT2 + noff;

    #define LOAD_STAGE(s) do {                                                 \
        __half* st_ = smh + ((s) % 3) * STG;                                   \
        _Pragma("unroll")                                                      \
        for (int j = 0; j < 3; ++j) {                                          \
            int ci = tid + 256 * j;                                            \
            int row = ci >> 3, ch = ci & 7;                                    \
            cpa16s(smem_u32(st_ + row * 72 + ch * 8),                          \
                   A + (size_t)(bm0 + row) * KH + (s) * 64 + ch * 8);          \
        }                                                                      \
        _Pragma("unroll")                                                      \
        for (int j = 0; j < 8; ++j) {                                          \
            int ci = tid + 256 * j;                                            \
            int row = ci >> 5, ch = ci & 31;                                   \
            cpa16s(smem_u32(st_ + STA + row * 264 + ch * 8),                   \
                   B + (size_t)((s) * 64 + row) * HID + bn0 + ch * 8);         \
        }                                                                      \
        asm volatile("cp.async.commit_group;" ::: "memory");                   \
    } while (0)

    const int mbase = (warp >> 2) * 48;     // warp tile 48x64, warp grid 2m x 4n
    const int nbase = (warp & 3) * 64;
    const int lrow  = lane & 15;
    const int lcol  = (lane >> 4) << 3;

    float acc[3][8][4];
    #pragma unroll
    for (int a = 0; a < 3; ++a)
        #pragma unroll
        for (int b = 0; b < 8; ++b)
            #pragma unroll
            for (int c = 0; c < 4; ++c) acc[a][b][c] = 0.f;

    LOAD_STAGE(0);
    LOAD_STAGE(1);

    constexpr int NIT = KH / 64;   // 16
    #pragma unroll 1
    for (int s = 0; s < NIT; ++s) {
        if (s + 1 < NIT) asm volatile("cp.async.wait_group 1;" ::: "memory");
        else             asm volatile("cp.async.wait_group 0;" ::: "memory");
        __syncthreads();

        const __half* st = smh + (s % 3) * STG;
        #pragma unroll
        for (int ks = 0; ks < 64; ks += 16) {
            unsigned bf[8][2];
            #pragma unroll
            for (int ntp = 0; ntp < 4; ++ntp) {
                unsigned t4[4];
                ldsm4t(t4, st + STA + (ks + lrow) * 264 + nbase + ntp * 16 + lcol);
                bf[ntp * 2][0]     = t4[0];  bf[ntp * 2][1]     = t4[1];
                bf[ntp * 2 + 1][0] = t4[2];  bf[ntp * 2 + 1][1] = t4[3];
            }
            unsigned af[3][4];
            #pragma unroll
            for (int mt = 0; mt < 3; ++mt)
                ldsm4(af[mt], st + (mbase + mt * 16 + lrow) * 72 + ks + lcol);
            #pragma unroll
            for (int mt = 0; mt < 3; ++mt)
                #pragma unroll
                for (int nt = 0; nt < 8; ++nt)
                    mma16816h(acc[mt][nt], af[mt], bf[nt]);
        }
        if (s + 2 < NIT) LOAD_STAGE(s + 2);
    }

    // ---- epilogue ----
    const int g  = lane >> 2;
    const int tg = lane & 3;
    #pragma unroll
    for (int mt = 0; mt < 3; ++mt) {
        #pragma unroll
        for (int nt = 0; nt < 8; ++nt) {
            int r0 = bm0 + mbase + mt * 16 + g;
            int r1 = r0 + 8;
            int c  = bn0 + nbase + nt * 8 + tg * 2;
            float* a4 = acc[mt][nt];
            if (MODE == 0) {
                __half2 v0 = __floats2half2_rn(a4[0], a4[1]);
                __half2 v1 = __floats2half2_rn(a4[2], a4[3]);
                if (r0 < NN) *(__half2*)&g_h1[(size_t)r0 * HID + c] = v0;
                if (r1 < NN) *(__half2*)&g_h1[(size_t)r1 * HID + c] = v1;
            } else {
                if (c < COUT) {
                    float2 v0 = make_float2(a4[0] + bias0[c], a4[1] + bias0[c + 1]);
                    float2 v1 = make_float2(a4[2] + bias0[c], a4[3] + bias0[c + 1]);
                    if (r0 < NN) {
                        *(float2*)&Cout[(size_t)r0 * COUT + c] = v0;                   // z
                        *(float2*)&Cout[(size_t)(NN + r0) * COUT + c] = v0;            // mu
                    }
                    if (r1 < NN) {
                        *(float2*)&Cout[(size_t)r1 * COUT + c] = v1;
                        *(float2*)&Cout[(size_t)(NN + r1) * COUT + c] = v1;
                    }
                } else {
                    int cs = c - COUT;
                    float2 v0 = make_float2(a4[0] + bias1[cs], a4[1] + bias1[cs + 1]);
                    float2 v1 = make_float2(a4[2] + bias1[cs], a4[3] + bias1[cs + 1]);
                    if (r0 < NN) *(float2*)&Cout[(size_t)(2 * NN + r0) * COUT + cs] = v0;  // logstd
                    if (r1 < NN) *(float2*)&Cout[(size_t)(2 * NN + r1) * COUT + cs] = v1;
                }
            }
        }
    }
    #undef LOAD_STAGE
}

// ---------------- column-strip aggregation (fp16 gather, f32 accumulate) ----------------
// Strip covers 256 columns = 128 half2; one block per node, 128 threads.
// agg1: g_h2[:,strip] = fp16(leakyrelu(A_norm @ g_h1[:,strip] + b1[strip]))
__global__ void __launch_bounds__(128)
k_agg1(const float* __restrict__ bias, int strip) {
    const int i  = blockIdx.x;
    const int c2 = (strip << 7) + threadIdx.x;        // half2 column index [0,512)
    const float dv = g_dinv[i];
    const float sw = dv * dv;
    const __half2* __restrict__ base = (const __half2*)g_h1;

    float2 f = __half22float2(base[(size_t)i * 512 + c2]);
    float a0 = sw * f.x, a1 = sw * f.y;

    const int beg = g_rowptr[i];
    const int end = g_rowptr[i + 1];
    #pragma unroll 4
    for (int e = beg; e < end; ++e) {
        const float w = g_wt[e];
        float2 r = __half22float2(base[(size_t)g_cols[e] * 512 + c2]);
        a0 = fmaf(w, r.x, a0);
        a1 = fmaf(w, r.y, a1);
    }
    const int c = c2 * 2;
    a0 += bias[c];     a0 = (a0 > 0.f) ? a0 : SLOPE * a0;
    a1 += bias[c + 1]; a1 = (a1 > 0.f) ? a1 : SLOPE * a1;
    ((__half2*)g_h2)[(size_t)i * 512 + c2] = __floats2half2_rn(a0, a1);
}

// agg2: g_a2h[:,strip] = fp16(A_norm @ g_h2[:,strip])
__global__ void __launch_bounds__(128)
k_agg2(int strip) {
    const int i  = blockIdx.x;
    const int c2 = (strip << 7) + threadIdx.x;
    const float dv = g_dinv[i];
    const float sw = dv * dv;
    const __half2* __restrict__ base = (const __half2*)g_h2;

    float2 f = __half22float2(base[(size_t)i * 512 + c2]);
    float a0 = sw * f.x, a1 = sw * f.y;

    const int beg = g_rowptr[i];
    const int end = g_rowptr[i + 1];
    #pragma unroll 4
    for (int e = beg; e < end; ++e) {
        const float w = g_wt[e];
        float2 r = __half22float2(base[(size_t)g_cols[e] * 512 + c2]);
        a0 = fmaf(w, r.x, a0);
        a1 = fmaf(w, r.y, a1);
    }
    ((__half2*)g_a2h)[(size_t)i * 512 + c2] = __floats2half2_rn(a0, a1);
}

// ---------------- launch ----------------
extern "C" void kernel_launch(void* const* d_in, const int* in_sizes, int n_in,
                              void* d_out, int out_size) {
    const float* x   = (const float*)d_in[0];
    const void*  edg = d_in[1];
    const float* W1  = (const float*)d_in[2];
    const float* b1  = (const float*)d_in[3];
    const float* Wm  = (const float*)d_in[4];
    const float* bm  = (const float*)d_in[5];
    const float* Ws  = (const float*)d_in[6];
    const float* bs  = (const float*)d_in[7];
    const float* gw  = (const float*)d_in[8];
    const float* gb  = (const float*)d_in[9];
    const float* gms = (const float*)d_in[10];
    float* out = (float*)d_out;

    // Lazily create streams + events on the first (non-capture) call.
    static cudaStream_t s_e = nullptr, s_w = nullptr, s_a = nullptr;
    static cudaEvent_t  ev_fork = nullptr, ev_w = nullptr, ev_join = nullptr, ev_agg = nullptr;
    static cudaEvent_t  ev_g1[4] = {nullptr, nullptr, nullptr, nullptr};
    if (s_e == nullptr) {
        cudaStreamCreateWithFlags(&s_e, cudaStreamNonBlocking);
        cudaStreamCreateWithFlags(&s_w, cudaStreamNonBlocking);
        cudaStreamCreateWithFlags(&s_a, cudaStreamNonBlocking);
        cudaEventCreateWithFlags(&ev_fork, cudaEventDisableTiming);
        cudaEventCreateWithFlags(&ev_w,    cudaEventDisableTiming);
        cudaEventCreateWithFlags(&ev_join, cudaEventDisableTiming);
        cudaEventCreateWithFlags(&ev_agg,  cudaEventDisableTiming);
        for (int s = 0; s < 4; ++s)
            cudaEventCreateWithFlags(&ev_g1[s], cudaEventDisableTiming);
    }

    constexpr int DSMEM = (MT * 72 + 64 * 264) * 3 * 2;   // 142848 bytes
    cudaFuncSetAttribute(k_mma<0>, cudaFuncAttributeMaxDynamicSharedMemorySize, DSMEM);
    cudaFuncSetAttribute(k_mma<1>, cudaFuncAttributeMaxDynamicSharedMemorySize, DSMEM);

    // fork root
    cudaEventRecord(ev_fork, 0);

    // ---- weight stream: B-plane conversion ----
    cudaStreamWaitEvent(s_w, ev_fork, 0);
    k_build_w<<<(CIN * HID / 4 + 255) / 256, 256, 0, s_w>>>(W1, Wm, Ws);
    cudaEventRecord(ev_w, s_w);

    // ---- edge stream: CSR construction ----
    cudaStreamWaitEvent(s_e, ev_fork, 0);
    k_zero_cnt<<<(NN + 255) / 256, 256, 0, s_e>>>();
    k_convert<<<(EE + 255) / 256, 256, 0, s_e>>>(edg);
    k_scan<<<1, 1024, 0, s_e>>>();
    k_fill<<<(EE + 255) / 256, 256, 0, s_e>>>();
    cudaEventRecord(ev_join, s_e);

    // ---- main stream: dense chain (starts immediately — stats is atomic-free) ----
    k_stats<<<PB, 256>>>(x);
    k_fin<<<8, 128>>>(gw, gb, gms);
    k_build_a1<<<(NN * CIN / 4 + 255) / 256, 256>>>(x);

    // layer 1: h = graphnorm(x) @ W1, split into 4 N-strips with per-strip events
    cudaStreamWaitEvent(0, ev_w, 0);
    dim3 gs(1, MTILES);
    for (int s = 0; s < 4; ++s) {
        k_mma<0><<<gs, 256, DSMEM>>>(nullptr, nullptr, nullptr, s * NT2);
        cudaEventRecord(ev_g1[s], 0);
    }

    // ---- agg stream: per-strip agg1 -> agg2 pipelined against GEMM1 strips ----
    cudaStreamWaitEvent(s_a, ev_join, 0);
    for (int s = 0; s < 4; ++s) {
        cudaStreamWaitEvent(s_a, ev_g1[s], 0);
        k_agg1<<<NN, 128, 0, s_a>>>(b1, s);
        k_agg2<<<NN, 128, 0, s_a>>>(s);
    }
    cudaEventRecord(ev_agg, s_a);

    // layer 2: out = A2 @ [Wm|Ws] + bias   (z = mu duplicated)
    cudaStreamWaitEvent(0, ev_agg, 0);
    dim3 g2(HID / NT2, MTILES);
    k_mma<1><<<g2, 256, DSMEM>>>(bm, bs, out, 0);
}

// round 14
// speedup vs baseline: 1.1519x; 1.1519x over previous
#include <cuda_runtime.h>
#include <cuda_fp16.h>
#include <cstdint>

#define NN   10000
#define EE   160000
#define CIN  1024
#define HID  1024
#define COUT 512
#define KH   1024
#define MPAD 10112           // padded row allocation (>= 105*96 = 10080)
#define MT   96              // CTA M tile
#define NT2  256             // CTA N tile
#define MTILES 105           // ceil(10000/96)
#define PB   200             // stats partial blocks
#define GN_EPS 1e-5f
#define SLOPE  0.1f

// ---------------- scratch (static device globals; no runtime alloc) ----------------
__device__ __half g_h1[(size_t)NN * HID];           // h = GEMM1 out (fp16)
__device__ __half g_h2[(size_t)NN * HID];           // agg1 out (fp16)
__device__ __half g_a1h[(size_t)MPAD * KH];         // GEMM1 A (fp16)
__device__ __half g_a2h[(size_t)MPAD * KH];         // GEMM2 A = agg2 out (fp16)
__device__ __half g_b1h[(size_t)KH * HID];          // GEMM1 B [k][n] = fp16(W1)
__device__ __half g_b2h[(size_t)KH * HID];          // GEMM2 B [k][n] = fp16([Wm|Ws])
__device__ float g_alpha[CIN];
__device__ float g_beta[CIN];
__device__ float g_ps[(size_t)PB * CIN];            // stats partial sums
__device__ float g_pq[(size_t)PB * CIN];            // stats partial sumsq
__device__ float g_dinv[NN];
__device__ int   g_cnt[NN];
__device__ int   g_rowptr[NN + 1];
__device__ int   g_cur[NN];
__device__ int   g_srcs[EE];
__device__ int   g_dsts[EE];
__device__ int   g_cols[EE];
__device__ float g_wt[EE];

// ---------------- PTX helpers ----------------
__device__ __forceinline__ unsigned smem_u32(const void* p) {
    return (unsigned)__cvta_generic_to_shared(p);
}
__device__ __forceinline__ void cpa16s(unsigned dst, const void* src) {
    asm volatile("cp.async.cg.shared.global [%0], [%1], 16;" :: "r"(dst), "l"(src) : "memory");
}
__device__ __forceinline__ void ldsm4(unsigned* r, const void* p) {
    unsigned a = smem_u32(p);
    asm volatile("ldmatrix.sync.aligned.m8n8.x4.shared.b16 {%0,%1,%2,%3}, [%4];"
                 : "=r"(r[0]), "=r"(r[1]), "=r"(r[2]), "=r"(r[3]) : "r"(a));
}
__device__ __forceinline__ void ldsm4t(unsigned* r, const void* p) {
    unsigned a = smem_u32(p);
    asm volatile("ldmatrix.sync.aligned.m8n8.x4.trans.shared.b16 {%0,%1,%2,%3}, [%4];"
                 : "=r"(r[0]), "=r"(r[1]), "=r"(r[2]), "=r"(r[3]) : "r"(a));
}
__device__ __forceinline__ void mma16816h(float* d, const unsigned* a, const unsigned* b) {
    asm volatile("mma.sync.aligned.m16n8k16.row.col.f32.f16.f16.f32 "
                 "{%0,%1,%2,%3}, {%4,%5,%6,%7}, {%8,%9}, {%0,%1,%2,%3};"
                 : "+f"(d[0]), "+f"(d[1]), "+f"(d[2]), "+f"(d[3])
                 : "r"(a[0]), "r"(a[1]), "r"(a[2]), "r"(a[3]), "r"(b[0]), "r"(b[1]));
}

// ---------------- edge-chain kernels (side stream) ----------------
__global__ void k_zero_cnt() {
    int i = blockIdx.x * blockDim.x + threadIdx.x;
    if (i < NN) g_cnt[i] = 0;
}

// convert + degree count; int64/int32 detection done per-block (L1-hot)
__global__ void k_convert(const void* __restrict__ edges) {
    __shared__ int sh_is64;
    if (threadIdx.x == 0) {
        const int* e = (const int*)edges;
        int is64 = 1;
        for (int j = 0; j < 64; ++j)
            if (e[2 * j + 1] != 0) { is64 = 0; break; }
        sh_is64 = is64;
    }
    __syncthreads();
    int i = blockIdx.x * blockDim.x + threadIdx.x;
    if (i >= EE) return;
    int s, d;
    if (sh_is64) {
        const long long* e = (const long long*)edges;
        s = (int)e[i];  d = (int)e[EE + i];
    } else {
        const int* e = (const int*)edges;
        s = e[i];  d = e[EE + i];
    }
    g_srcs[i] = s;  g_dsts[i] = d;
    atomicAdd(&g_cnt[d], 1);
}

// blocked single-pass exclusive scan (1024 thr x 10 elems) -> rowptr/cur/dinv
__global__ void k_scan() {
    __shared__ int sh[1024];
    const int t = threadIdx.x;
    const int base = t * 10;
    int v[10], loc[10], run = 0;
    #pragma unroll
    for (int j = 0; j < 10; ++j) {
        int idx = base + j;
        v[j] = (idx < NN) ? g_cnt[idx] : 0;
        loc[j] = run;
        run += v[j];
    }
    sh[t] = run;
    __syncthreads();
    for (int off = 1; off < 1024; off <<= 1) {
        int add = (t >= off) ? sh[t - off] : 0;
        __syncthreads();
        sh[t] += add;
        __syncthreads();
    }
    int pre = (t > 0) ? sh[t - 1] : 0;
    #pragma unroll
    for (int j = 0; j < 10; ++j) {
        int idx = base + j;
        if (idx < NN) {
            int ex = pre + loc[j];
            g_rowptr[idx] = ex;
            g_cur[idx]    = ex;
            g_dinv[idx]   = rsqrtf((float)(v[j] + 1));   // +1 self loop
        }
    }
    if (t == 1023) g_rowptr[NN] = sh[1023];
}

__global__ void k_fill() {
    int i = blockIdx.x * blockDim.x + threadIdx.x;
    if (i >= EE) return;
    int d = g_dsts[i];
    int s = g_srcs[i];
    int pos = atomicAdd(&g_cur[d], 1);
    g_cols[pos] = s;
    g_wt[pos]   = g_dinv[s] * g_dinv[d];
}

// ---------------- dense-chain kernels ----------------
// stats: atomic-free partials (no zero dependency — launches at t=0)
__global__ void k_stats(const float* __restrict__ x) {
    const int t = threadIdx.x;
    const int b = blockIdx.x;
    float s0 = 0.f, s1 = 0.f, s2 = 0.f, s3 = 0.f;
    float q0 = 0.f, q1 = 0.f, q2 = 0.f, q3 = 0.f;
    for (int r = b; r < NN; r += PB) {
        const float* row = x + (size_t)r * CIN;
        float v0 = row[t];       s0 += v0; q0 += v0 * v0;
        float v1 = row[t + 256]; s1 += v1; q1 += v1 * v1;
        float v2 = row[t + 512]; s2 += v2; q2 += v2 * v2;
        float v3 = row[t + 768]; s3 += v3; q3 += v3 * v3;
    }
    float* ps = g_ps + (size_t)b * CIN;
    float* pq = g_pq + (size_t)b * CIN;
    ps[t]       = s0; pq[t]       = q0;
    ps[t + 256] = s1; pq[t + 256] = q1;
    ps[t + 512] = s2; pq[t + 512] = q2;
    ps[t + 768] = s3; pq[t + 768] = q3;
}

// reduce partials + compute alpha/beta
__global__ void k_fin(const float* __restrict__ gw,
                      const float* __restrict__ gb,
                      const float* __restrict__ gms) {
    int i = blockIdx.x * blockDim.x + threadIdx.x;   // 8 x 128 = 1024
    if (i >= CIN) return;
    float sum = 0.f, sq = 0.f;
    #pragma unroll 8
    for (int j = 0; j < PB; ++j) {
        sum += g_ps[(size_t)j * CIN + i];
        sq  += g_pq[(size_t)j * CIN + i];
    }
    float mean = sum * (1.0f / NN);
    float ex2  = sq  * (1.0f / NN);
    float s    = gms[i];
    float var  = ex2 - 2.f * s * mean * mean + s * s * mean * mean;
    float rstd = rsqrtf(var + GN_EPS);
    float al   = rstd * gw[i];
    g_alpha[i] = al;
    g_beta[i]  = gb[i] - s * mean * al;
}

// A1 = fp16(affine(x)), 4-wide vectorized
__global__ void k_build_a1(const float* __restrict__ x) {
    int i = blockIdx.x * blockDim.x + threadIdx.x;    // over NN*CIN/4
    if (i >= NN * CIN / 4) return;
    int k4 = (i & 255) << 2;
    float4 xv = ((const float4*)x)[i];
    float a0 = g_alpha[k4],     a1 = g_alpha[k4 + 1];
    float a2 = g_alpha[k4 + 2], a3 = g_alpha[k4 + 3];
    float b0 = g_beta[k4],      b1 = g_beta[k4 + 1];
    float b2 = g_beta[k4 + 2],  b3 = g_beta[k4 + 3];
    __half2 h0 = __floats2half2_rn(fmaf(xv.x, a0, b0), fmaf(xv.y, a1, b1));
    __half2 h1 = __floats2half2_rn(fmaf(xv.z, a2, b2), fmaf(xv.w, a3, b3));
    __half2* o = (__half2*)g_a1h + (size_t)i * 2;
    o[0] = h0;  o[1] = h1;
}

// B planes, 4-wide vectorized: g_b1h = fp16(W1); g_b2h = fp16([Wm|Ws])
__global__ void k_build_w(const float* __restrict__ W1,
                          const float* __restrict__ Wm,
                          const float* __restrict__ Ws) {
    int i = blockIdx.x * blockDim.x + threadIdx.x;    // over CIN*HID/4
    if (i >= CIN * HID / 4) return;
    int k  = i >> 8;
    int n4 = (i & 255) << 2;
    float4 w1 = ((const float4*)W1)[i];
    __half2* o1 = (__half2*)g_b1h + (size_t)i * 2;
    o1[0] = __floats2half2_rn(w1.x, w1.y);
    o1[1] = __floats2half2_rn(w1.z, w1.w);
    float4 w2 = (n4 < COUT)
        ? *(const float4*)(Wm + (size_t)k * COUT + n4)
        : *(const float4*)(Ws + (size_t)k * COUT + n4 - COUT);
    __half2* o2 = (__half2*)g_b2h + (size_t)i * 2;
    o2[0] = __floats2half2_rn(w2.x, w2.y);
    o2[1] = __floats2half2_rn(w2.z, w2.w);
}

// ---------------- fp16 tensor-core GEMM ----------------
// CTA 96x256, 256 threads (8 warps of 48x64), BK=64, 3-stage cp.async ring.
// Grid (4,105) = 420 CTAs, 1 CTA/SM (143KB smem) -> 2.84 waves.
// MODE 0: g_h1 (fp16) = A1 @ B1        MODE 1: out (f32) = A2 @ B2 + bias
template <int MODE>
__global__ void __launch_bounds__(256, 1)
k_mma(const float* __restrict__ bias0, const float* __restrict__ bias1,
      float* __restrict__ Cout)
{
    extern __shared__ __half smh[];
    const __half* __restrict__ A = (MODE == 0) ? g_a1h : g_a2h;
    const __half* __restrict__ B = (MODE == 0) ? g_b1h : g_b2h;

    constexpr int STA = MT * 72;             // A tile 96x64, pad 64->72
    constexpr int STB = 64 * 264;            // B tile 64x256, pad 256->264
    constexpr int STG = STA + STB;           // 23808 halfs / stage

    const int tid  = threadIdx.x;
    const int warp = tid >> 5;
    const int lane = tid & 31;
    const int bm0  = blockIdx.y * MT;
    const int bn0  = blockIdx.x * NT2;

    #define LOAD_STAGE(s) do {                                                 \
        __half* st_ = smh + ((s) % 3) * STG;                                   \
        _Pragma("unroll")                                                      \
        for (int j = 0; j < 3; ++j) {                                          \
            int ci = tid + 256 * j;                                            \
            int row = ci >> 3, ch = ci & 7;                                    \
            cpa16s(smem_u32(st_ + row * 72 + ch * 8),                          \
                   A + (size_t)(bm0 + row) * KH + (s) * 64 + ch * 8);          \
        }                                                                      \
        _Pragma("unroll")                                                      \
        for (int j = 0; j < 8; ++j) {                                          \
            int ci = tid + 256 * j;                                            \
            int row = ci >> 5, ch = ci & 31;                                   \
            cpa16s(smem_u32(st_ + STA + row * 264 + ch * 8),                   \
                   B + (size_t)((s) * 64 + row) * HID + bn0 + ch * 8);         \
        }                                                                      \
        asm volatile("cp.async.commit_group;" ::: "memory");                   \
    } while (0)

    const int mbase = (warp >> 2) * 48;     // warp tile 48x64, warp grid 2m x 4n
    const int nbase = (warp & 3) * 64;
    const int lrow  = lane & 15;
    const int lcol  = (lane >> 4) << 3;

    float acc[3][8][4];
    #pragma unroll
    for (int a = 0; a < 3; ++a)
        #pragma unroll
        for (int b = 0; b < 8; ++b)
            #pragma unroll
            for (int c = 0; c < 4; ++c) acc[a][b][c] = 0.f;

    LOAD_STAGE(0);
    LOAD_STAGE(1);

    constexpr int NIT = KH / 64;   // 16
    #pragma unroll 1
    for (int s = 0; s < NIT; ++s) {
        if (s + 1 < NIT) asm volatile("cp.async.wait_group 1;" ::: "memory");
        else             asm volatile("cp.async.wait_group 0;" ::: "memory");
        __syncthreads();

        const __half* st = smh + (s % 3) * STG;
        #pragma unroll
        for (int ks = 0; ks < 64; ks += 16) {
            unsigned bf[8][2];
            #pragma unroll
            for (int ntp = 0; ntp < 4; ++ntp) {
                unsigned t4[4];
                ldsm4t(t4, st + STA + (ks + lrow) * 264 + nbase + ntp * 16 + lcol);
                bf[ntp * 2][0]     = t4[0];  bf[ntp * 2][1]     = t4[1];
                bf[ntp * 2 + 1][0] = t4[2];  bf[ntp * 2 + 1][1] = t4[3];
            }
            unsigned af[3][4];
            #pragma unroll
            for (int mt = 0; mt < 3; ++mt)
                ldsm4(af[mt], st + (mbase + mt * 16 + lrow) * 72 + ks + lcol);
            #pragma unroll
            for (int mt = 0; mt < 3; ++mt)
                #pragma unroll
                for (int nt = 0; nt < 8; ++nt)
                    mma16816h(acc[mt][nt], af[mt], bf[nt]);
        }
        if (s + 2 < NIT) LOAD_STAGE(s + 2);
    }

    // ---- epilogue ----
    const int g  = lane >> 2;
    const int tg = lane & 3;
    #pragma unroll
    for (int mt = 0; mt < 3; ++mt) {
        #pragma unroll
        for (int nt = 0; nt < 8; ++nt) {
            int r0 = bm0 + mbase + mt * 16 + g;
            int r1 = r0 + 8;
            int c  = bn0 + nbase + nt * 8 + tg * 2;
            float* a4 = acc[mt][nt];
            if (MODE == 0) {
                __half2 v0 = __floats2half2_rn(a4[0], a4[1]);
                __half2 v1 = __floats2half2_rn(a4[2], a4[3]);
                if (r0 < NN) *(__half2*)&g_h1[(size_t)r0 * HID + c] = v0;
                if (r1 < NN) *(__half2*)&g_h1[(size_t)r1 * HID + c] = v1;
            } else {
                if (c < COUT) {
                    float2 v0 = make_float2(a4[0] + bias0[c], a4[1] + bias0[c + 1]);
                    float2 v1 = make_float2(a4[2] + bias0[c], a4[3] + bias0[c + 1]);
                    if (r0 < NN) {
                        *(float2*)&Cout[(size_t)r0 * COUT + c] = v0;                   // z
                        *(float2*)&Cout[(size_t)(NN + r0) * COUT + c] = v0;            // mu
                    }
                    if (r1 < NN) {
                        *(float2*)&Cout[(size_t)r1 * COUT + c] = v1;
                        *(float2*)&Cout[(size_t)(NN + r1) * COUT + c] = v1;
                    }
                } else {
                    int cs = c - COUT;
                    float2 v0 = make_float2(a4[0] + bias1[cs], a4[1] + bias1[cs + 1]);
                    float2 v1 = make_float2(a4[2] + bias1[cs], a4[3] + bias1[cs + 1]);
                    if (r0 < NN) *(float2*)&Cout[(size_t)(2 * NN + r0) * COUT + cs] = v0;  // logstd
                    if (r1 < NN) *(float2*)&Cout[(size_t)(2 * NN + r1) * COUT + cs] = v1;
                }
            }
        }
    }
    #undef LOAD_STAGE
}

// ---------------- aggregation (fp16 gather, f32 accumulate) ----------------
// agg1: g_h2 = fp16(leakyrelu(A_norm @ g_h1 + b1))
__global__ void __launch_bounds__(256)
k_agg1(const float* __restrict__ bias) {
    const int i = blockIdx.x;
    const int t = threadIdx.x;
    const float dv = g_dinv[i];
    const float sw = dv * dv;

    const __half2* self = (const __half2*)(g_h1 + (size_t)i * HID);
    float2 f0 = __half22float2(self[t]);
    float2 f1 = __half22float2(self[t + 256]);
    float a0 = sw * f0.x, a1 = sw * f0.y, a2 = sw * f1.x, a3 = sw * f1.y;

    const int beg = g_rowptr[i];
    const int end = g_rowptr[i + 1];
    #pragma unroll 2
    for (int e = beg; e < end; ++e) {
        const int   s = g_cols[e];
        const float w = g_wt[e];
        const __half2* r = (const __half2*)(g_h1 + (size_t)s * HID);
        float2 r0 = __half22float2(r[t]);
        float2 r1 = __half22float2(r[t + 256]);
        a0 = fmaf(w, r0.x, a0);
        a1 = fmaf(w, r0.y, a1);
        a2 = fmaf(w, r1.x, a2);
        a3 = fmaf(w, r1.y, a3);
    }
    a0 += bias[2 * t];       a0 = (a0 > 0.f) ? a0 : SLOPE * a0;
    a1 += bias[2 * t + 1];   a1 = (a1 > 0.f) ? a1 : SLOPE * a1;
    a2 += bias[2 * t + 512]; a2 = (a2 > 0.f) ? a2 : SLOPE * a2;
    a3 += bias[2 * t + 513]; a3 = (a3 > 0.f) ? a3 : SLOPE * a3;

    __half2* o = (__half2*)(g_h2 + (size_t)i * HID);
    o[t]       = __floats2half2_rn(a0, a1);
    o[t + 256] = __floats2half2_rn(a2, a3);
}

// agg2: g_a2h = fp16(A_norm @ g_h2)   (GEMM2 A input)
__global__ void __launch_bounds__(256)
k_agg2() {
    const int i = blockIdx.x;
    const int t = threadIdx.x;
    const float dv = g_dinv[i];
    const float sw = dv * dv;

    const __half2* self = (const __half2*)(g_h2 + (size_t)i * HID);
    float2 f0 = __half22float2(self[t]);
    float2 f1 = __half22float2(self[t + 256]);
    float a0 = sw * f0.x, a1 = sw * f0.y, a2 = sw * f1.x, a3 = sw * f1.y;

    const int beg = g_rowptr[i];
    const int end = g_rowptr[i + 1];
    #pragma unroll 2
    for (int e = beg; e < end; ++e) {
        const int   s = g_cols[e];
        const float w = g_wt[e];
        const __half2* r = (const __half2*)(g_h2 + (size_t)s * HID);
        float2 r0 = __half22float2(r[t]);
        float2 r1 = __half22float2(r[t + 256]);
        a0 = fmaf(w, r0.x, a0);
        a1 = fmaf(w, r0.y, a1);
        a2 = fmaf(w, r1.x, a2);
        a3 = fmaf(w, r1.y, a3);
    }

    __half2* o = (__half2*)(g_a2h + (size_t)i * KH);
    o[t]       = __floats2half2_rn(a0, a1);
    o[t + 256] = __floats2half2_rn(a2, a3);
}

// ---------------- launch ----------------
extern "C" void kernel_launch(void* const* d_in, const int* in_sizes, int n_in,
                              void* d_out, int out_size) {
    const float* x   = (const float*)d_in[0];
    const void*  edg = d_in[1];
    const float* W1  = (const float*)d_in[2];
    const float* b1  = (const float*)d_in[3];
    const float* Wm  = (const float*)d_in[4];
    const float* bm  = (const float*)d_in[5];
    const float* Ws  = (const float*)d_in[6];
    const float* bs  = (const float*)d_in[7];
    const float* gw  = (const float*)d_in[8];
    const float* gb  = (const float*)d_in[9];
    const float* gms = (const float*)d_in[10];
    float* out = (float*)d_out;

    // Lazily create streams + events on the first (non-capture) call.
    static cudaStream_t s_e = nullptr, s_w = nullptr;
    static cudaEvent_t  ev_fork = nullptr, ev_w = nullptr, ev_join = nullptr;
    if (s_e == nullptr) {
        cudaStreamCreateWithFlags(&s_e, cudaStreamNonBlocking);
        cudaStreamCreateWithFlags(&s_w, cudaStreamNonBlocking);
        cudaEventCreateWithFlags(&ev_fork, cudaEventDisableTiming);
        cudaEventCreateWithFlags(&ev_w,    cudaEventDisableTiming);
        cudaEventCreateWithFlags(&ev_join, cudaEventDisableTiming);
    }

    constexpr int DSMEM = (MT * 72 + 64 * 264) * 3 * 2;   // 142848 bytes
    cudaFuncSetAttribute(k_mma<0>, cudaFuncAttributeMaxDynamicSharedMemorySize, DSMEM);
    cudaFuncSetAttribute(k_mma<1>, cudaFuncAttributeMaxDynamicSharedMemorySize, DSMEM);

    // fork root
    cudaEventRecord(ev_fork, 0);

    // ---- weight stream: B-plane conversion ----
    cudaStreamWaitEvent(s_w, ev_fork, 0);
    k_build_w<<<(CIN * HID / 4 + 255) / 256, 256, 0, s_w>>>(W1, Wm, Ws);
    cudaEventRecord(ev_w, s_w);

    // ---- edge stream: CSR construction ----
    cudaStreamWaitEvent(s_e, ev_fork, 0);
    k_zero_cnt<<<(NN + 255) / 256, 256, 0, s_e>>>();
    k_convert<<<(EE + 255) / 256, 256, 0, s_e>>>(edg);
    k_scan<<<1, 1024, 0, s_e>>>();
    k_fill<<<(EE + 255) / 256, 256, 0, s_e>>>();
    cudaEventRecord(ev_join, s_e);

    // ---- main stream: dense chain (starts immediately — stats is atomic-free) ----
    k_stats<<<PB, 256>>>(x);
    k_fin<<<8, 128>>>(gw, gb, gms);
    k_build_a1<<<(NN * CIN / 4 + 255) / 256, 256>>>(x);

    // layer 1: h = graphnorm(x) @ W1   (single launch, wave-balanced grid)
    cudaStreamWaitEvent(0, ev_w, 0);
    dim3 g1(HID / NT2, MTILES);     // (4, 105)
    k_mma<0><<<g1, 256, DSMEM>>>(nullptr, nullptr, nullptr);

    // join: aggregations need the edge CSR
    cudaStreamWaitEvent(0, ev_join, 0);
    k_agg1<<<NN, 256>>>(b1);
    k_agg2<<<NN, 256>>>();

    // layer 2: out = A2 @ [Wm|Ws] + bias   (z = mu duplicated)
    dim3 g2(HID / NT2, MTILES);
    k_mma<1><<<g2, 256, DSMEM>>>(bm, bs, out);
}